// round 2
// baseline (speedup 1.0000x reference)
#include <cuda_runtime.h>
#include <cuda_bf16.h>

#define N_NODES 50000
#define E_EDGES 800000
#define D 128

// Scratch (device globals — no allocation allowed)
__device__ float g_deg[N_NODES];
__device__ float g_dinv[N_NODES];
__device__ float g_xlin[(size_t)N_NODES * D];

// ---------------------------------------------------------------------------
// 1) deg init: self-loop contributes 1 to every node's degree
__global__ void k_init_deg() {
    int i = blockIdx.x * blockDim.x + threadIdx.x;
    if (i < N_NODES) g_deg[i] = 1.0f;
}

// 2) degree count over destination nodes
__global__ void k_count(const int* __restrict__ dst) {
    int e = blockIdx.x * blockDim.x + threadIdx.x;
    if (e < E_EDGES) atomicAdd(&g_deg[dst[e]], 1.0f);
}

// 3) dinv = rsqrt(deg)  (deg >= 1 always, so no zero-guard needed)
__global__ void k_dinv() {
    int i = blockIdx.x * blockDim.x + threadIdx.x;
    if (i < N_NODES) g_dinv[i] = rsqrtf(g_deg[i]);
}

// ---------------------------------------------------------------------------
// 4) SGEMM x_lin = x @ W^T, fused self-loop epilogue:
//      out[i][:] = x_lin[i][:] * dinv[i]^2 + b
//    Tile: BM=128, BN=128(full), BK=8, 256 threads, 8x8 micro-tile per thread.
__global__ __launch_bounds__(256, 2)
void k_gemm(const float* __restrict__ x, const float* __restrict__ W,
            const float* __restrict__ b, float* __restrict__ out) {
    __shared__ float As[8][132];
    __shared__ float Bs[8][132];

    const int tid = threadIdx.x;
    const int m0  = blockIdx.x * 128;
    const int tx  = tid & 15;        // 0..15 -> col group
    const int ty  = tid >> 4;        // 0..15 -> row group

    const int lr = tid >> 1;         // 0..127: row within tile (A) / W row (B)
    const int kg = (tid & 1) * 4;    // 0 or 4: k sub-chunk

    float acc[8][8];
#pragma unroll
    for (int i = 0; i < 8; i++)
#pragma unroll
        for (int j = 0; j < 8; j++) acc[i][j] = 0.0f;

    for (int k0 = 0; k0 < D; k0 += 8) {
        // Load A tile (x rows m0..m0+127, k-cols k0..k0+7), transposed into smem
        float4 av = make_float4(0.f, 0.f, 0.f, 0.f);
        int gr = m0 + lr;
        if (gr < N_NODES) av = *(const float4*)(x + (size_t)gr * D + k0 + kg);
        As[kg + 0][lr] = av.x; As[kg + 1][lr] = av.y;
        As[kg + 2][lr] = av.z; As[kg + 3][lr] = av.w;

        // Load B tile: Bs[k][n] = W[n][k0+k]  (W row n = output column n)
        float4 bv = *(const float4*)(W + (size_t)lr * D + k0 + kg);
        Bs[kg + 0][lr] = bv.x; Bs[kg + 1][lr] = bv.y;
        Bs[kg + 2][lr] = bv.z; Bs[kg + 3][lr] = bv.w;

        __syncthreads();

#pragma unroll
        for (int k = 0; k < 8; k++) {
            float ar[8], br[8];
#pragma unroll
            for (int i = 0; i < 8; i++) ar[i] = As[k][ty * 8 + i];
#pragma unroll
            for (int j = 0; j < 8; j++) br[j] = Bs[k][tx * 8 + j];
#pragma unroll
            for (int i = 0; i < 8; i++)
#pragma unroll
                for (int j = 0; j < 8; j++) acc[i][j] += ar[i] * br[j];
        }
        __syncthreads();
    }

    // Epilogue: write x_lin, and out = x_lin * dinv^2 + b (self-loop message)
#pragma unroll
    for (int i = 0; i < 8; i++) {
        int row = m0 + ty * 8 + i;
        if (row >= N_NODES) continue;
        float di  = g_dinv[row];
        float di2 = di * di;
#pragma unroll
        for (int jj = 0; jj < 2; jj++) {
            int col = tx * 8 + jj * 4;
            float4 v = make_float4(acc[i][jj*4+0], acc[i][jj*4+1],
                                   acc[i][jj*4+2], acc[i][jj*4+3]);
            *(float4*)(g_xlin + (size_t)row * D + col) = v;
            float4 bb = *(const float4*)(b + col);
            float4 o  = make_float4(v.x * di2 + bb.x, v.y * di2 + bb.y,
                                    v.z * di2 + bb.z, v.w * di2 + bb.w);
            *(float4*)(out + (size_t)row * D + col) = o;
        }
    }
}

// ---------------------------------------------------------------------------
// 5) Edge scatter: one warp per edge. Each lane handles 4 floats (float4),
//    vector reduction red.global.add.v4.f32 into out[dst].
__global__ __launch_bounds__(256)
void k_edges(const int* __restrict__ src, const int* __restrict__ dst,
             float* __restrict__ out) {
    int w    = (blockIdx.x * blockDim.x + threadIdx.x) >> 5;
    int lane = threadIdx.x & 31;
    if (w >= E_EDGES) return;

    int s = __ldg(src + w);
    int d = __ldg(dst + w);
    float norm = g_dinv[s] * g_dinv[d];

    float4 v = *(const float4*)(g_xlin + (size_t)s * D + lane * 4);
    float* p = out + (size_t)d * D + lane * 4;
    asm volatile("red.global.add.v4.f32 [%0], {%1, %2, %3, %4};" ::
                 "l"(p),
                 "f"(v.x * norm), "f"(v.y * norm),
                 "f"(v.z * norm), "f"(v.w * norm)
                 : "memory");
}

// ---------------------------------------------------------------------------
extern "C" void kernel_launch(void* const* d_in, const int* in_sizes, int n_in,
                              void* d_out, int out_size) {
    const float* x  = (const float*)d_in[0];
    const int*   ei = (const int*)d_in[1];       // [2, E]: row 0 = src, row 1 = dst
    const float* W  = (const float*)d_in[2];
    const float* b  = (const float*)d_in[3];
    float* out = (float*)d_out;

    const int* src = ei;
    const int* dst = ei + E_EDGES;

    k_init_deg<<<(N_NODES + 255) / 256, 256>>>();
    k_count<<<(E_EDGES + 255) / 256, 256>>>(dst);
    k_dinv<<<(N_NODES + 255) / 256, 256>>>();
    k_gemm<<<(N_NODES + 127) / 128, 256>>>(x, W, b, out);

    // one warp per edge: E * 32 threads total; 800000*32/256 = 100000 blocks
    long long total = (long long)E_EDGES * 32;
    int blocks = (int)((total + 255) / 256);
    k_edges<<<blocks, 256>>>(src, dst, out);
}